// round 2
// baseline (speedup 1.0000x reference)
#include <cuda_runtime.h>
#include <cuda_bf16.h>
#include <cstdint>

// ============================================================================
// ComplexConv2Deffangle: two paths over x[:,0] and x[:,1]:
//   path0 (rot): depthwise 3x3 (w1^2/sum(w1^2))  -> 1x1 (w2^2/sum(w2^2))
//   path1 (abs): log(x+eps) -> depthwise 3x3 (w1^2/rowsum) -> 1x1 (w2^2/rowsum) -> exp
// x: (32,2,64,64,64) f32, w1: (64,9), w2: (128,64)
// out: (32,2,128,62,62) f32
// ============================================================================

#define EPS 1e-6f
#define NB 32
#define C_IN 64
#define C_OUT 128
#define H 64
#define W 64
#define OX 62
#define OY 62
#define LTOT (OX * OY)   // 3844

// Normalized weights, prepared by prep kernel.
// g_w1n[path][c][k]       : depthwise weights
// g_w2n[path][c][o]       : pointwise weights TRANSPOSED (c-major) and
//                           pre-duplicated into float2 {w,w} for f32x2 FMA.
__device__ float  g_w1n[2][C_IN][9];
__device__ float2 g_w2n[2][C_IN][C_OUT];

// ---------------------------------------------------------------------------
// f32x2 packed helpers (sm_100+ PTX)
// ---------------------------------------------------------------------------
__device__ __forceinline__ void ffma2(unsigned long long& d,
                                      unsigned long long a,
                                      unsigned long long b) {
    asm("fma.rn.f32x2 %0, %1, %2, %0;" : "+l"(d) : "l"(a), "l"(b));
}
__device__ __forceinline__ float2 unpack2(unsigned long long a) {
    float2 f;
    asm("mov.b64 {%0, %1}, %2;" : "=f"(f.x), "=f"(f.y) : "l"(a));
    return f;
}

// ---------------------------------------------------------------------------
// Prep kernel: normalize weights. One block, 256 threads.
// ---------------------------------------------------------------------------
__global__ void prep_weights_kernel(const float* __restrict__ w1,
                                    const float* __restrict__ w2) {
    __shared__ float red[256];
    __shared__ float s1_sh, s2_sh;
    __shared__ float s1r[C_IN];    // per-row sums of w1^2
    __shared__ float s2r[C_OUT];   // per-row sums of w2^2
    int tid = threadIdx.x;

    // global sum w1^2 (576 elems)
    float a = 0.f;
    for (int i = tid; i < C_IN * 9; i += 256) { float t = w1[i]; a += t * t; }
    red[tid] = a; __syncthreads();
    for (int s = 128; s > 0; s >>= 1) { if (tid < s) red[tid] += red[tid + s]; __syncthreads(); }
    if (tid == 0) s1_sh = red[0];
    __syncthreads();

    // global sum w2^2 (8192 elems)
    a = 0.f;
    for (int i = tid; i < C_OUT * C_IN; i += 256) { float t = w2[i]; a += t * t; }
    red[tid] = a; __syncthreads();
    for (int s = 128; s > 0; s >>= 1) { if (tid < s) red[tid] += red[tid + s]; __syncthreads(); }
    if (tid == 0) s2_sh = red[0];

    // row sums
    if (tid < C_IN) {
        float s = 0.f;
        for (int k = 0; k < 9; k++) { float t = w1[tid * 9 + k]; s += t * t; }
        s1r[tid] = s;
    }
    if (tid < C_OUT) {
        float s = 0.f;
        for (int c = 0; c < C_IN; c++) { float t = w2[tid * C_IN + c]; s += t * t; }
        s2r[tid] = s;
    }
    __syncthreads();

    float inv_s1 = 1.f / s1_sh;
    float inv_s2 = 1.f / s2_sh;

    for (int i = tid; i < C_IN * 9; i += 256) {
        int c = i / 9;
        float t = w1[i]; float t2 = t * t;
        ((float*)g_w1n[0])[i] = t2 * inv_s1;
        ((float*)g_w1n[1])[i] = t2 / s1r[c];
    }
    for (int i = tid; i < C_OUT * C_IN; i += 256) {
        int o = i >> 6, c = i & 63;
        float t = w2[i]; float t2 = t * t;
        float ga = t2 * inv_s2;
        float gb = t2 / s2r[o];
        g_w2n[0][c][o] = make_float2(ga, ga);
        g_w2n[1][c][o] = make_float2(gb, gb);
    }
}

// ---------------------------------------------------------------------------
// Main fused kernel.
// grid: (31 row-pairs, 32 batch, 2 path), 256 threads.
// Dynamic smem layout (floats):
//   [0      .. 16384) Wt  : float2[64][128]  (w2 transposed, duplicated) 64 KB
//   [16384  .. 32768) xin : float[64][4][64] (4 input rows x 64 ch)      64 KB
//   [32768  .. 40960) v2  : float2[64][64]   (depthwise, row-pair pack)  32 KB
//   [40960  .. 41536) w1s : float[64][9]
// total = 166,144 bytes
// ---------------------------------------------------------------------------
__global__ __launch_bounds__(256, 1)
void cce_main_kernel(const float* __restrict__ x, float* __restrict__ out) {
    extern __shared__ float sm[];
    float2* Wt  = (float2*)sm;          // 8192 float2
    float*  xin = sm + 16384;           // 16384 floats
    float2* v2  = (float2*)(sm + 32768);// 4096 float2
    float*  w1s = sm + 40960;           // 576 floats

    const int tid = threadIdx.x;
    const int r0  = blockIdx.x * 2;     // output rows r0, r0+1
    const int b   = blockIdx.y;
    const int p   = blockIdx.z;

    // ---- stage 0: load weights into smem ----
    {
        const float4* wsrc = (const float4*)g_w2n[p];   // 4096 float4
        float4* wdst = (float4*)Wt;
        #pragma unroll
        for (int i = 0; i < 16; i++) wdst[tid + i * 256] = wsrc[tid + i * 256];
        const float* w1src = (const float*)g_w1n[p];
        for (int i = tid; i < C_IN * 9; i += 256) w1s[i] = w1src[i];
    }

    // ---- stage 1: load 4 input rows x 64 channels (16384 floats, float4) ----
    {
        const float* xbase = x + (size_t)(b * 2 + p) * (C_IN * H * W) + r0 * W;
        #pragma unroll
        for (int i = 0; i < 16; i++) {
            int idx = tid + i * 256;        // 0..4095 float4s
            int c = idx >> 6;               // channel
            int q = idx & 63;               // float4 within 4 rows (256 floats)
            float4 v = ((const float4*)(xbase + (size_t)c * (H * W)))[q];
            if (p == 1) {
                v.x = __logf(v.x + EPS);
                v.y = __logf(v.y + EPS);
                v.z = __logf(v.z + EPS);
                v.w = __logf(v.w + EPS);
            }
            ((float4*)(xin + c * 256))[q] = v;
        }
    }
    __syncthreads();

    // ---- stage 2: depthwise 3x3 for rows r0, r0+1 -> v2[c][l] = {row0,row1} ----
    #pragma unroll
    for (int i = 0; i < 16; i++) {
        int idx = tid + i * 256;            // 0..4095
        int c = idx >> 6;
        int l = idx & 63;
        if (l < OY) {
            const float* xc = xin + c * 256 + l;
            const float* wc = w1s + c * 9;
            float a0 = 0.f, a1 = 0.f;
            #pragma unroll
            for (int rr = 0; rr < 3; rr++) {
                #pragma unroll
                for (int j = 0; j < 3; j++) {
                    float w = wc[rr * 3 + j];
                    a0 = fmaf(xc[rr * 64 + j],      w, a0);
                    a1 = fmaf(xc[rr * 64 + 64 + j], w, a1);
                }
            }
            v2[c * 64 + l] = make_float2(a0, a1);
        } else {
            v2[c * 64 + l] = make_float2(0.f, 0.f);
        }
    }
    __syncthreads();

    // ---- stage 3: pointwise GEMM with packed f32x2 FMA ----
    // thread -> 16 out-channels (warp-owned), l-cols {lane, lane+32}, rows packed.
    const int lane = tid & 31;
    const int warp = tid >> 5;
    const int ob   = warp * 16;

    unsigned long long acc[32];
    #pragma unroll
    for (int i = 0; i < 32; i++) acc[i] = 0ull;

    const unsigned long long* v2u = (const unsigned long long*)v2;
    #pragma unroll 4
    for (int c = 0; c < C_IN; c++) {
        unsigned long long va = v2u[c * 64 + lane];
        unsigned long long vb = v2u[c * 64 + lane + 32];
        const ulonglong2* wr = (const ulonglong2*)(Wt + c * C_OUT + ob);
        #pragma unroll
        for (int q = 0; q < 8; q++) {
            ulonglong2 w = wr[q];
            ffma2(acc[2 * q],          va, w.x);
            ffma2(acc[2 * q + 1],      va, w.y);
            ffma2(acc[16 + 2 * q],     vb, w.x);
            ffma2(acc[16 + 2 * q + 1], vb, w.y);
        }
    }

    // ---- stage 4: epilogue + coalesced stores ----
    float* obase = out + (size_t)(b * 2 + p) * (C_OUT * LTOT) + (size_t)r0 * OY;
    #pragma unroll
    for (int i = 0; i < 16; i++) {
        int o = ob + i;
        float* orow = obase + (size_t)o * LTOT;
        float2 f = unpack2(acc[i]);          // l = lane (always < 62)
        if (p == 1) { f.x = __expf(f.x); f.y = __expf(f.y); }
        orow[lane]      = f.x;               // row r0
        orow[OY + lane] = f.y;               // row r0+1
        if (lane < OY - 32) {                // l = lane+32 < 62
            float2 g = unpack2(acc[16 + i]);
            if (p == 1) { g.x = __expf(g.x); g.y = __expf(g.y); }
            orow[lane + 32]      = g.x;
            orow[OY + lane + 32] = g.y;
        }
    }
}

// ---------------------------------------------------------------------------
extern "C" void kernel_launch(void* const* d_in, const int* in_sizes, int n_in,
                              void* d_out, int out_size) {
    const float* x  = (const float*)d_in[0];
    const float* w1 = (const float*)d_in[1];
    const float* w2 = (const float*)d_in[2];
    float* out = (float*)d_out;

    prep_weights_kernel<<<1, 256>>>(w1, w2);

    const int smem_bytes = 41536 * 4;  // 166,144
    cudaFuncSetAttribute(cce_main_kernel,
                         cudaFuncAttributeMaxDynamicSharedMemorySize, smem_bytes);
    dim3 grid(OX / 2, NB, 2);          // (31, 32, 2)
    cce_main_kernel<<<grid, 256, smem_bytes>>>(x, out);
}

// round 5
// speedup vs baseline: 1.5706x; 1.5706x over previous
#include <cuda_runtime.h>
#include <cuda_bf16.h>
#include <cstdint>

// ============================================================================
// ComplexConv2Deffangle: two paths over x[:,0] and x[:,1]:
//   path0 (rot): depthwise 3x3 (w1^2/sum(w1^2))  -> 1x1 (w2^2/sum(w2^2))
//   path1 (abs): log(x+eps) -> depthwise 3x3 (w1^2/rowsum) -> 1x1 (w2^2/rowsum) -> exp
// x: (32,2,64,64,64) f32, w1: (64,9), w2: (128,64)
// out: (32,2,128,62,62) f32
// ============================================================================

#define EPS 1e-6f
#define NB 32
#define C_IN 64
#define C_OUT 128
#define H 64
#define W 64
#define OX 62
#define OY 62
#define LTOT (OX * OY)   // 3844
#define CCHUNK 32        // channels staged per smem chunk

// Normalized weights, prepared by prep kernel.
// g_w1n[path][c][k] : depthwise weights
// g_w2n[path][c][o] : pointwise weights TRANSPOSED (c-major), plain float.
__device__ float g_w1n[2][C_IN][9];
__device__ float g_w2n[2][C_IN][C_OUT];

// ---------------------------------------------------------------------------
// f32x2 packed helpers (sm_100+ PTX)
// ---------------------------------------------------------------------------
__device__ __forceinline__ void ffma2(unsigned long long& d,
                                      unsigned long long a,
                                      unsigned long long b) {
    asm("fma.rn.f32x2 %0, %1, %2, %0;" : "+l"(d) : "l"(a), "l"(b));
}
__device__ __forceinline__ unsigned long long dup2(float s) {
    unsigned long long d;
    asm("mov.b64 %0, {%1, %1};" : "=l"(d) : "f"(s));
    return d;
}
__device__ __forceinline__ float2 unpack2(unsigned long long a) {
    float2 f;
    asm("mov.b64 {%0, %1}, %2;" : "=f"(f.x), "=f"(f.y) : "l"(a));
    return f;
}

// ---------------------------------------------------------------------------
// Prep kernel: normalize weights. One block, 256 threads.
// ---------------------------------------------------------------------------
__global__ void prep_weights_kernel(const float* __restrict__ w1,
                                    const float* __restrict__ w2) {
    __shared__ float red[256];
    __shared__ float s1_sh, s2_sh;
    __shared__ float s1r[C_IN];    // per-row sums of w1^2
    __shared__ float s2r[C_OUT];   // per-row sums of w2^2
    int tid = threadIdx.x;

    float a = 0.f;
    for (int i = tid; i < C_IN * 9; i += 256) { float t = w1[i]; a += t * t; }
    red[tid] = a; __syncthreads();
    for (int s = 128; s > 0; s >>= 1) { if (tid < s) red[tid] += red[tid + s]; __syncthreads(); }
    if (tid == 0) s1_sh = red[0];
    __syncthreads();

    a = 0.f;
    for (int i = tid; i < C_OUT * C_IN; i += 256) { float t = w2[i]; a += t * t; }
    red[tid] = a; __syncthreads();
    for (int s = 128; s > 0; s >>= 1) { if (tid < s) red[tid] += red[tid + s]; __syncthreads(); }
    if (tid == 0) s2_sh = red[0];

    if (tid < C_IN) {
        float s = 0.f;
        for (int k = 0; k < 9; k++) { float t = w1[tid * 9 + k]; s += t * t; }
        s1r[tid] = s;
    }
    if (tid < C_OUT) {
        float s = 0.f;
        for (int c = 0; c < C_IN; c++) { float t = w2[tid * C_IN + c]; s += t * t; }
        s2r[tid] = s;
    }
    __syncthreads();

    float inv_s1 = 1.f / s1_sh;
    float inv_s2 = 1.f / s2_sh;

    for (int i = tid; i < C_IN * 9; i += 256) {
        int c = i / 9;
        float t = w1[i]; float t2 = t * t;
        ((float*)g_w1n[0])[i] = t2 * inv_s1;
        ((float*)g_w1n[1])[i] = t2 / s1r[c];
    }
    for (int i = tid; i < C_OUT * C_IN; i += 256) {
        int o = i >> 6, c = i & 63;
        float t = w2[i]; float t2 = t * t;
        g_w2n[0][c][o] = t2 * inv_s2;
        g_w2n[1][c][o] = t2 / s2r[o];
    }
}

// ---------------------------------------------------------------------------
// Main fused kernel.
// grid: (31 row-pairs, 32 batch, 2 path), 256 threads, 2 blocks/SM.
// Dynamic smem layout (float offsets):
//   [0     .. 8192 ) Wt  : float[64][128]   (w2 transposed, plain)   32 KB
//   [8192  .. 16384) xin : float[32][4][64] (CCHUNK ch x 4 rows)     32 KB
//   [16384 .. 24576) v2  : float2[64][64]   ({row0,row1} per (c,l))  32 KB
//   [24576 .. 25152) w1s : float[64][9]
// total = 100,608 bytes -> 2 blocks/SM (201 KB / 228 KB)
// ---------------------------------------------------------------------------
__global__ __launch_bounds__(256, 2)
void cce_main_kernel(const float* __restrict__ x, float* __restrict__ out) {
    extern __shared__ float sm[];
    float*  Wt  = sm;                    // 8192 floats
    float*  xin = sm + 8192;             // 8192 floats (one chunk)
    float2* v2  = (float2*)(sm + 16384); // 4096 float2
    float*  w1s = sm + 24576;            // 576 floats

    const int tid = threadIdx.x;
    const int r0  = blockIdx.x * 2;      // output rows r0, r0+1
    const int b   = blockIdx.y;
    const int p   = blockIdx.z;

    // ---- stage 0: weights into smem ----
    {
        const float4* wsrc = (const float4*)g_w2n[p];   // 2048 float4
        float4* wdst = (float4*)Wt;
        #pragma unroll
        for (int i = 0; i < 8; i++) wdst[tid + i * 256] = wsrc[tid + i * 256];
        const float* w1src = (const float*)g_w1n[p];
        for (int i = tid; i < C_IN * 9; i += 256) w1s[i] = w1src[i];
    }

    // ---- stages 1+2: chunked input staging + depthwise ----
    const float* xbase = x + (size_t)(b * 2 + p) * (C_IN * H * W) + r0 * W;
    #pragma unroll
    for (int chunk = 0; chunk < C_IN / CCHUNK; chunk++) {
        // load CCHUNK channels x 4 rows (2048 float4)
        #pragma unroll
        for (int i = 0; i < 8; i++) {
            int idx = tid + i * 256;          // 0..2047 float4s
            int cl  = idx >> 6;               // local channel 0..31
            int q   = idx & 63;               // float4 within 4 rows
            int c   = chunk * CCHUNK + cl;
            float4 v = ((const float4*)(xbase + (size_t)c * (H * W)))[q];
            if (p == 1) {
                v.x = __logf(v.x + EPS);
                v.y = __logf(v.y + EPS);
                v.z = __logf(v.z + EPS);
                v.w = __logf(v.w + EPS);
            }
            ((float4*)(xin + cl * 256))[q] = v;
        }
        __syncthreads();

        // depthwise 3x3 for rows r0, r0+1 over this chunk
        #pragma unroll
        for (int i = 0; i < 8; i++) {
            int idx = tid + i * 256;          // 0..2047
            int cl  = idx >> 6;
            int l   = idx & 63;
            int c   = chunk * CCHUNK + cl;
            if (l < OY) {
                const float* xc = xin + cl * 256 + l;
                const float* wc = w1s + c * 9;
                float a0 = 0.f, a1 = 0.f;
                #pragma unroll
                for (int rr = 0; rr < 3; rr++) {
                    #pragma unroll
                    for (int j = 0; j < 3; j++) {
                        float w = wc[rr * 3 + j];
                        a0 = fmaf(xc[rr * 64 + j],      w, a0);
                        a1 = fmaf(xc[rr * 64 + 64 + j], w, a1);
                    }
                }
                v2[c * 64 + l] = make_float2(a0, a1);
            } else {
                v2[c * 64 + l] = make_float2(0.f, 0.f);
            }
        }
        __syncthreads();
    }

    // ---- stage 3: pointwise GEMM, f32x2 packing over OUT-CHANNEL PAIRS ----
    // warp owns 16 out-channels = 8 pairs; thread covers cols {lane, lane+32},
    // rows r0/r1. acc[pair*4 + {colA_r0, colA_r1, colB_r0, colB_r1}].
    const int lane = tid & 31;
    const int warp = tid >> 5;
    const int ob   = warp * 16;

    unsigned long long acc[32];
    #pragma unroll
    for (int i = 0; i < 32; i++) acc[i] = 0ull;

    const ulonglong2* WtU = (const ulonglong2*)Wt;   // 32 ull2 per c-row
    #pragma unroll 2
    for (int c = 0; c < C_IN; c++) {
        float2 va = v2[c * 64 + lane];
        float2 vb = v2[c * 64 + lane + 32];
        unsigned long long a0 = dup2(va.x);   // col lane,   row r0
        unsigned long long a1 = dup2(va.y);   // col lane,   row r1
        unsigned long long b0 = dup2(vb.x);   // col lane+32, row r0
        unsigned long long b1 = dup2(vb.y);   // col lane+32, row r1
        const ulonglong2* wr = WtU + c * 32 + warp * 4;
        #pragma unroll
        for (int q = 0; q < 4; q++) {
            ulonglong2 w = wr[q];             // 4 out-ch = 2 pairs (broadcast)
            ffma2(acc[q * 8 + 0], a0, w.x);
            ffma2(acc[q * 8 + 1], a1, w.x);
            ffma2(acc[q * 8 + 2], b0, w.x);
            ffma2(acc[q * 8 + 3], b1, w.x);
            ffma2(acc[q * 8 + 4], a0, w.y);
            ffma2(acc[q * 8 + 5], a1, w.y);
            ffma2(acc[q * 8 + 6], b0, w.y);
            ffma2(acc[q * 8 + 7], b1, w.y);
        }
    }

    // ---- stage 4: epilogue + coalesced stores ----
    float* obase = out + (size_t)(b * 2 + p) * (C_OUT * LTOT) + (size_t)r0 * OY;
    #pragma unroll
    for (int pr = 0; pr < 8; pr++) {
        float2 c00 = unpack2(acc[pr * 4 + 0]);   // col lane,    row0: {o0,o1}
        float2 c01 = unpack2(acc[pr * 4 + 1]);   // col lane,    row1
        int o0 = ob + 2 * pr;
        float* orow0 = obase + (size_t)o0 * LTOT;
        float* orow1 = orow0 + LTOT;
        if (p == 1) {
            c00.x = __expf(c00.x); c00.y = __expf(c00.y);
            c01.x = __expf(c01.x); c01.y = __expf(c01.y);
        }
        orow0[lane]      = c00.x;   orow1[lane]      = c00.y;
        orow0[OY + lane] = c01.x;   orow1[OY + lane] = c01.y;
        if (lane < OY - 32) {
            float2 c10 = unpack2(acc[pr * 4 + 2]);   // col lane+32, row0
            float2 c11 = unpack2(acc[pr * 4 + 3]);   // col lane+32, row1
            if (p == 1) {
                c10.x = __expf(c10.x); c10.y = __expf(c10.y);
                c11.x = __expf(c11.x); c11.y = __expf(c11.y);
            }
            orow0[lane + 32]      = c10.x;   orow1[lane + 32]      = c10.y;
            orow0[OY + lane + 32] = c11.x;   orow1[OY + lane + 32] = c11.y;
        }
    }
}

// ---------------------------------------------------------------------------
extern "C" void kernel_launch(void* const* d_in, const int* in_sizes, int n_in,
                              void* d_out, int out_size) {
    const float* x  = (const float*)d_in[0];
    const float* w1 = (const float*)d_in[1];
    const float* w2 = (const float*)d_in[2];
    float* out = (float*)d_out;

    prep_weights_kernel<<<1, 256>>>(w1, w2);

    const int smem_bytes = 25152 * 4;  // 100,608
    cudaFuncSetAttribute(cce_main_kernel,
                         cudaFuncAttributeMaxDynamicSharedMemorySize, smem_bytes);
    dim3 grid(OX / 2, NB, 2);          // (31, 32, 2)
    cce_main_kernel<<<grid, 256, smem_bytes>>>(x, out);
}